// round 16
// baseline (speedup 1.0000x reference)
#include <cuda_runtime.h>
#include <cuda_bf16.h>
#include <mma.h>
#include <cstdint>

using namespace nvcuda;

// ---------------- problem-size constants (dataset: N=100000, E=1600000, D=64) ----
#define MAXN 100000
#define DD   64
#define DD2  128

// ---------------- scratch (device-code-only references!) ---------------------------
__device__ float g_agg[(size_t)MAXN * DD];     // 25.6 MB  segment sums
__device__ float g_deg[MAXN];
__device__ float g_t1[(size_t)MAXN * DD2];     // 51.2 MB  pre-BN GEMM1 output (bias-free; BN shift-invariant)
__device__ float g_sum1[DD2], g_sumsq1[DD2];
__device__ float g_sum2[DD],  g_sumsq2[DD];

__device__ __forceinline__ uint32_t bfpack(float a, float b) {
    __nv_bfloat162 t = __floats2bfloat162_rn(a, b);
    return *reinterpret_cast<uint32_t*>(&t);
}

// ---------------- kernels 0a/0b/0c: zero scratch (split so edge is launch #4) ------
__global__ void zero_agg_kernel(int n) {
    int stride = gridDim.x * blockDim.x;
    int i = blockIdx.x * blockDim.x + threadIdx.x;
    int total4 = n * 16;
    float4 z4 = make_float4(0.f, 0.f, 0.f, 0.f);
    for (int idx = i; idx < total4; idx += stride)
        reinterpret_cast<float4*>(g_agg)[idx] = z4;
}
__global__ void zero_deg_kernel(int n) {
    int stride = gridDim.x * blockDim.x;
    int i = blockIdx.x * blockDim.x + threadIdx.x;
    for (int idx = i; idx < n; idx += stride) g_deg[idx] = 0.0f;
}
__global__ void zero_stats_kernel() {
    int i = threadIdx.x;
    if (i < DD2) { g_sum1[i] = 0.0f; g_sumsq1[i] = 0.0f; }
    if (i < DD)  { g_sum2[i] = 0.0f; g_sumsq2[i] = 0.0f; }
}

// ---------------- kernel 1: edge gather + scatter (4 thr/edge, 4 float4 each) ------
// MLP = 8 outstanding 16B loads per thread; indices leader-loaded + shfl broadcast.
__global__ void __launch_bounds__(256) edge_kernel(
    const float4* __restrict__ nf, const float4* __restrict__ ef,
    const int* __restrict__ src, const int* __restrict__ dst, int E)
{
    int t = blockIdx.x * blockDim.x + threadIdx.x;
    int lane = threadIdx.x & 31;
    int e = t >> 2;            // 4 threads per edge
    int q = t & 3;             // handles q, q+4, q+8, q+12

    // leader lane of each 4-lane group loads indices; broadcast before any exit
    int sld = 0, dld = 0;
    if ((lane & 3) == 0 && e < E) { sld = __ldg(src + e); dld = __ldg(dst + e); }
    int s = __shfl_sync(0xffffffffu, sld, lane & ~3);
    int d = __shfl_sync(0xffffffffu, dld, lane & ~3);
    if (e >= E) return;

    size_t eb = (size_t)e * 16;
    size_t sb = (size_t)s * 16;
    // issue all 8 loads before any use (MLP=8)
    float4 b0 = __ldcs(ef + eb + q);
    float4 b1 = __ldcs(ef + eb + q + 4);
    float4 b2 = __ldcs(ef + eb + q + 8);
    float4 b3 = __ldcs(ef + eb + q + 12);
    float4 a0 = __ldg(nf + sb + q);
    float4 a1 = __ldg(nf + sb + q + 4);
    float4 a2 = __ldg(nf + sb + q + 8);
    float4 a3 = __ldg(nf + sb + q + 12);

    float4 v0 = make_float4(a0.x + b0.x, a0.y + b0.y, a0.z + b0.z, a0.w + b0.w);
    float4 v1 = make_float4(a1.x + b1.x, a1.y + b1.y, a1.z + b1.z, a1.w + b1.w);
    float4 v2 = make_float4(a2.x + b2.x, a2.y + b2.y, a2.z + b2.z, a2.w + b2.w);
    float4 v3 = make_float4(a3.x + b3.x, a3.y + b3.y, a3.z + b3.z, a3.w + b3.w);
    float4* aggp = reinterpret_cast<float4*>(g_agg) + (size_t)d * 16;
    atomicAdd(aggp + q,      v0);
    atomicAdd(aggp + q + 4,  v1);
    atomicAdd(aggp + q + 8,  v2);
    atomicAdd(aggp + q + 12, v3);
    if (q == 0) atomicAdd(&g_deg[d], 1.0f);
}

// ---------------- kernel 2: combine + GEMM1 via WMMA bf16x3 + fused stats ----------
// A = h split hi/lo [128 rows][64 k] stride 72; B = W1 split [64 k][128 n] stride 136
#define AS1 72
#define BS1 136
__global__ void __launch_bounds__(256) gemm1_kernel(
    const float* __restrict__ nf, const float* __restrict__ eps,
    const float* __restrict__ W1, int N)
{
    extern __shared__ char smraw[];
    __nv_bfloat16* aHi = reinterpret_cast<__nv_bfloat16*>(smraw);
    __nv_bfloat16* aLo = aHi + 128 * AS1;
    __nv_bfloat16* bHi = aLo + 128 * AS1;
    __nv_bfloat16* bLo = bHi + 64 * BS1;
    float* stage = reinterpret_cast<float*>(smraw);   // reused after MMA
    __shared__ float s_sum[DD2], s_sumsq[DD2];

    int tid  = threadIdx.x;
    int w    = tid >> 5;
    int lane = tid & 31;
    int r0   = blockIdx.x * 128;
    float epsv = 1.0f + eps[0];
    if (tid < DD2) { s_sum[tid] = 0.f; s_sumsq[tid] = 0.f; }

    // build A: h = (1+eps)*nf + agg/max(deg,1), split hi/lo (coalesced)
    for (int c = tid; c < 128 * 16; c += 256) {
        int row = c >> 4;              // 0..127
        int kc  = (c & 15) << 2;       // 0,4,...,60
        int rg  = r0 + row;
        float4 v = make_float4(0.f, 0.f, 0.f, 0.f);
        if (rg < N) {
            float4 a = *reinterpret_cast<const float4*>(nf + (size_t)rg * DD + kc);
            float4 g = *reinterpret_cast<const float4*>(g_agg + (size_t)rg * DD + kc);
            float rd = 1.0f / fmaxf(g_deg[rg], 1.0f);
            v.x = epsv * a.x + g.x * rd;
            v.y = epsv * a.y + g.y * rd;
            v.z = epsv * a.z + g.z * rd;
            v.w = epsv * a.w + g.w * rd;
        }
        float hx = __bfloat162float(__float2bfloat16_rn(v.x));
        float hy = __bfloat162float(__float2bfloat16_rn(v.y));
        float hz = __bfloat162float(__float2bfloat16_rn(v.z));
        float hw = __bfloat162float(__float2bfloat16_rn(v.w));
        *reinterpret_cast<uint32_t*>(aHi + row * AS1 + kc)     = bfpack(hx, hy);
        *reinterpret_cast<uint32_t*>(aHi + row * AS1 + kc + 2) = bfpack(hz, hw);
        *reinterpret_cast<uint32_t*>(aLo + row * AS1 + kc)     = bfpack(v.x - hx, v.y - hy);
        *reinterpret_cast<uint32_t*>(aLo + row * AS1 + kc + 2) = bfpack(v.z - hz, v.w - hw);
    }

    // build B[k][n] = W1 (row-major [64][128] already k-major) — coalesced
    for (int c = tid; c < 64 * 64; c += 256) {
        int k  = c >> 6;
        int n2 = (c & 63) << 1;
        float w0 = __ldg(W1 + k * 128 + n2);
        float w1 = __ldg(W1 + k * 128 + n2 + 1);
        float h0 = __bfloat162float(__float2bfloat16_rn(w0));
        float h1 = __bfloat162float(__float2bfloat16_rn(w1));
        *reinterpret_cast<uint32_t*>(bHi + k * BS1 + n2) = bfpack(h0, h1);
        *reinterpret_cast<uint32_t*>(bLo + k * BS1 + n2) = bfpack(w0 - h0, w1 - h1);
    }
    __syncthreads();

    // MMA: warp w owns rows [w*16, w*16+16)
    int rbase = w * 16;
    wmma::fragment<wmma::accumulator, 16, 16, 16, float> acc[8];
#pragma unroll
    for (int j = 0; j < 8; j++) wmma::fill_fragment(acc[j], 0.0f);

#pragma unroll
    for (int k0 = 0; k0 < 64; k0 += 16) {
        wmma::fragment<wmma::matrix_a, 16, 16, 16, __nv_bfloat16, wmma::row_major> fah, fal;
        wmma::load_matrix_sync(fah, aHi + rbase * AS1 + k0, AS1);
        wmma::load_matrix_sync(fal, aLo + rbase * AS1 + k0, AS1);
#pragma unroll
        for (int j = 0; j < 8; j++) {
            wmma::fragment<wmma::matrix_b, 16, 16, 16, __nv_bfloat16, wmma::row_major> fbh, fbl;
            wmma::load_matrix_sync(fbh, bHi + k0 * BS1 + j * 16, BS1);
            wmma::load_matrix_sync(fbl, bLo + k0 * BS1 + j * 16, BS1);
            wmma::mma_sync(acc[j], fah, fbh, acc[j]);
            wmma::mma_sync(acc[j], fah, fbl, acc[j]);
            wmma::mma_sync(acc[j], fal, fbh, acc[j]);
        }
    }
    __syncthreads();   // done reading A/B; reuse smem as f32 staging

    float* st = stage + w * (16 * BS1);
#pragma unroll
    for (int j = 0; j < 8; j++)
        wmma::store_matrix_sync(st + j * 16, acc[j], BS1, wmma::mem_row_major);
    __syncwarp();

    // guarded copy to g_t1 + fused column stats (lane owns cols [lane*4, +4))
    {
        int col = lane << 2;
        float4 cs = make_float4(0.f, 0.f, 0.f, 0.f);
        float4 cq = make_float4(0.f, 0.f, 0.f, 0.f);
#pragma unroll
        for (int rr = 0; rr < 16; rr++) {
            int rg = r0 + rbase + rr;
            if (rg < N) {
                float4 v = *reinterpret_cast<float4*>(st + rr * BS1 + col);
                *reinterpret_cast<float4*>(g_t1 + (size_t)rg * DD2 + col) = v;
                cs.x += v.x; cs.y += v.y; cs.z += v.z; cs.w += v.w;
                cq.x += v.x * v.x; cq.y += v.y * v.y;
                cq.z += v.z * v.z; cq.w += v.w * v.w;
            }
        }
        atomicAdd(&s_sum[col + 0], cs.x); atomicAdd(&s_sum[col + 1], cs.y);
        atomicAdd(&s_sum[col + 2], cs.z); atomicAdd(&s_sum[col + 3], cs.w);
        atomicAdd(&s_sumsq[col + 0], cq.x); atomicAdd(&s_sumsq[col + 1], cq.y);
        atomicAdd(&s_sumsq[col + 2], cq.z); atomicAdd(&s_sumsq[col + 3], cq.w);
    }
    __syncthreads();
    if (tid < DD2) {
        atomicAdd(&g_sum1[tid], s_sum[tid]);
        atomicAdd(&g_sumsq1[tid], s_sumsq[tid]);
    }
}

// ---------------- kernel 3: BN1+ReLU + GEMM2, K=128 in TWO 64-halves ---------------
// smem per half: A 2x128x72 bf16 + B 2x64x72 bf16 = 55.3KB -> 4 blocks/SM.
#define AS2 72
#define BS2 72
__global__ void __launch_bounds__(256) gemm2_kernel(
    const float* __restrict__ W2,
    const float* __restrict__ gamma1, const float* __restrict__ beta1,
    float* __restrict__ out, int N, float invN)
{
    extern __shared__ char smraw[];
    __nv_bfloat16* aHi = reinterpret_cast<__nv_bfloat16*>(smraw);
    __nv_bfloat16* aLo = aHi + 128 * AS2;
    __nv_bfloat16* bHi = aLo + 128 * AS2;
    __nv_bfloat16* bLo = bHi + 64 * BS2;
    float* stage = reinterpret_cast<float*>(smraw);   // aliases A region
    __shared__ float s_scale[DD2], s_shift[DD2];
    __shared__ float s_sum[DD], s_sumsq[DD];

    int tid  = threadIdx.x;
    int w    = tid >> 5;
    int lane = tid & 31;
    int r0   = blockIdx.x * 128;

    if (tid < DD) { s_sum[tid] = 0.f; s_sumsq[tid] = 0.f; }
    if (tid < DD2) {
        float m = g_sum1[tid] * invN;
        float v = fmaxf(g_sumsq1[tid] * invN - m * m, 0.0f);
        float sc = __ldg(gamma1 + tid) * rsqrtf(v + 1e-5f);
        s_scale[tid] = sc;
        s_shift[tid] = __ldg(beta1 + tid) - m * sc;
    }

    int rbase = w * 16;
    wmma::fragment<wmma::accumulator, 16, 16, 16, float> acc[4];
#pragma unroll
    for (int j = 0; j < 4; j++) wmma::fill_fragment(acc[j], 0.0f);

#pragma unroll
    for (int kh = 0; kh < 2; kh++) {
        __syncthreads();   // covers s_scale on first pass, tile reuse after

        // build A half = relu(BN1(t1[:, kh*64 : +64])) split hi/lo (coalesced)
        for (int c = tid; c < 128 * 16; c += 256) {
            int row = c >> 4;              // 0..127
            int kl  = (c & 15) << 2;       // local k 0..60
            int kg  = kh * 64 + kl;
            int rg  = r0 + row;
            float4 v = make_float4(0.f, 0.f, 0.f, 0.f);
            if (rg < N) {
                float4 z = *reinterpret_cast<const float4*>(g_t1 + (size_t)rg * DD2 + kg);
                v.x = fmaxf(fmaf(z.x, s_scale[kg + 0], s_shift[kg + 0]), 0.f);
                v.y = fmaxf(fmaf(z.y, s_scale[kg + 1], s_shift[kg + 1]), 0.f);
                v.z = fmaxf(fmaf(z.z, s_scale[kg + 2], s_shift[kg + 2]), 0.f);
                v.w = fmaxf(fmaf(z.w, s_scale[kg + 3], s_shift[kg + 3]), 0.f);
            }
            float hx = __bfloat162float(__float2bfloat16_rn(v.x));
            float hy = __bfloat162float(__float2bfloat16_rn(v.y));
            float hz = __bfloat162float(__float2bfloat16_rn(v.z));
            float hw = __bfloat162float(__float2bfloat16_rn(v.w));
            *reinterpret_cast<uint32_t*>(aHi + row * AS2 + kl)     = bfpack(hx, hy);
            *reinterpret_cast<uint32_t*>(aHi + row * AS2 + kl + 2) = bfpack(hz, hw);
            *reinterpret_cast<uint32_t*>(aLo + row * AS2 + kl)     = bfpack(v.x - hx, v.y - hy);
            *reinterpret_cast<uint32_t*>(aLo + row * AS2 + kl + 2) = bfpack(v.z - hz, v.w - hw);
        }

        // build B half: k in [kh*64, +64) rows of W2[128][64], stride 72 (coalesced)
        for (int c = tid; c < 64 * 32; c += 256) {
            int k  = c >> 5;               // local k 0..63
            int n2 = (c & 31) << 1;
            int kg = kh * 64 + k;
            float w0 = __ldg(W2 + kg * 64 + n2);
            float w1 = __ldg(W2 + kg * 64 + n2 + 1);
            float h0 = __bfloat162float(__float2bfloat16_rn(w0));
            float h1 = __bfloat162float(__float2bfloat16_rn(w1));
            *reinterpret_cast<uint32_t*>(bHi + k * BS2 + n2) = bfpack(h0, h1);
            *reinterpret_cast<uint32_t*>(bLo + k * BS2 + n2) = bfpack(w0 - h0, w1 - h1);
        }
        __syncthreads();

#pragma unroll
        for (int k0 = 0; k0 < 64; k0 += 16) {
            wmma::fragment<wmma::matrix_a, 16, 16, 16, __nv_bfloat16, wmma::row_major> fah, fal;
            wmma::load_matrix_sync(fah, aHi + rbase * AS2 + k0, AS2);
            wmma::load_matrix_sync(fal, aLo + rbase * AS2 + k0, AS2);
#pragma unroll
            for (int j = 0; j < 4; j++) {
                wmma::fragment<wmma::matrix_b, 16, 16, 16, __nv_bfloat16, wmma::row_major> fbh, fbl;
                wmma::load_matrix_sync(fbh, bHi + k0 * BS2 + j * 16, BS2);
                wmma::load_matrix_sync(fbl, bLo + k0 * BS2 + j * 16, BS2);
                wmma::mma_sync(acc[j], fah, fbh, acc[j]);
                wmma::mma_sync(acc[j], fah, fbl, acc[j]);
                wmma::mma_sync(acc[j], fal, fbh, acc[j]);
            }
        }
    }
    __syncthreads();   // done with A/B; reuse smem as f32 staging

    float* st = stage + w * (16 * BS2);
#pragma unroll
    for (int j = 0; j < 4; j++)
        wmma::store_matrix_sync(st + j * 16, acc[j], BS2, wmma::mem_row_major);
    __syncwarp();

    // guarded copy to out + fused column stats (col = (lane&15)*4, row halves)
    {
        int col = (lane & 15) << 2;
        int rhalf = (lane >> 4) * 8;
        float4 cs = make_float4(0.f, 0.f, 0.f, 0.f);
        float4 cq = make_float4(0.f, 0.f, 0.f, 0.f);
#pragma unroll
        for (int rr = 0; rr < 8; rr++) {
            int r = rhalf + rr;
            int rg = r0 + rbase + r;
            if (rg < N) {
                float4 v = *reinterpret_cast<float4*>(st + r * BS2 + col);
                *reinterpret_cast<float4*>(out + (size_t)rg * DD + col) = v;
                cs.x += v.x; cs.y += v.y; cs.z += v.z; cs.w += v.w;
                cq.x += v.x * v.x; cq.y += v.y * v.y;
                cq.z += v.z * v.z; cq.w += v.w * v.w;
            }
        }
        atomicAdd(&s_sum[col + 0], cs.x); atomicAdd(&s_sum[col + 1], cs.y);
        atomicAdd(&s_sum[col + 2], cs.z); atomicAdd(&s_sum[col + 3], cs.w);
        atomicAdd(&s_sumsq[col + 0], cq.x); atomicAdd(&s_sumsq[col + 1], cq.y);
        atomicAdd(&s_sumsq[col + 2], cq.z); atomicAdd(&s_sumsq[col + 3], cq.w);
    }
    __syncthreads();
    if (tid < DD) {
        atomicAdd(&g_sum2[tid], s_sum[tid]);
        atomicAdd(&g_sumsq2[tid], s_sumsq[tid]);
    }
}

// ---------------- kernel 4: BN2 finalize (folded) + BN2 + ReLU in place ------------
__global__ void __launch_bounds__(256) bn2_kernel(
    float* __restrict__ out, const float* __restrict__ gamma2,
    const float* __restrict__ beta2, int N, float invN)
{
    __shared__ float s_scale2[DD], s_shift2[DD];
    int tid = threadIdx.x;
    if (tid < DD) {
        float m = g_sum2[tid] * invN;
        float v = fmaxf(g_sumsq2[tid] * invN - m * m, 0.0f);
        float sc = __ldg(gamma2 + tid) * rsqrtf(v + 1e-5f);
        s_scale2[tid] = sc;
        s_shift2[tid] = __ldg(beta2 + tid) - m * sc;
    }
    __syncthreads();

    int idx = blockIdx.x * blockDim.x + tid;
    int total = N * 16;
    if (idx >= total) return;
    int c = (idx & 15) << 2;
    float4 z = reinterpret_cast<float4*>(out)[idx];
    z.x = fmaxf(fmaf(z.x, s_scale2[c + 0], s_shift2[c + 0]), 0.f);
    z.y = fmaxf(fmaf(z.y, s_scale2[c + 1], s_shift2[c + 1]), 0.f);
    z.z = fmaxf(fmaf(z.z, s_scale2[c + 2], s_shift2[c + 2]), 0.f);
    z.w = fmaxf(fmaf(z.w, s_scale2[c + 3], s_shift2[c + 3]), 0.f);
    reinterpret_cast<float4*>(out)[idx] = z;
}

// ---------------- launch ------------------------------------------------------------
extern "C" void kernel_launch(void* const* d_in, const int* in_sizes, int n_in,
                              void* d_out, int out_size) {
    const float* node_feats = (const float*)d_in[0];
    const float* edge_feats = (const float*)d_in[1];
    const int*   src        = (const int*)d_in[2];
    const int*   dst        = (const int*)d_in[3];
    const float* eps        = (const float*)d_in[4];
    const float* W1         = (const float*)d_in[5];
    const float* gamma1     = (const float*)d_in[7];
    const float* beta1      = (const float*)d_in[8];
    const float* W2         = (const float*)d_in[9];
    const float* gamma2     = (const float*)d_in[11];
    const float* beta2      = (const float*)d_in[12];
    float* out = (float*)d_out;

    int N = in_sizes[0] / DD;
    int E = in_sizes[1] / DD;
    float invN = 1.0f / (float)N;

    size_t sm1 = (size_t)(2 * 128 * AS1 + 2 * 64 * BS1) * 2;    // 71680 B
    size_t sm2 = (size_t)(2 * 128 * AS2 + 2 * 64 * BS2) * 2;    // 55296 B
    cudaFuncSetAttribute(gemm1_kernel, cudaFuncAttributeMaxDynamicSharedMemorySize, (int)sm1);
    cudaFuncSetAttribute(gemm2_kernel, cudaFuncAttributeMaxDynamicSharedMemorySize, (int)sm2);

    zero_agg_kernel<<<4096, 256>>>(N);
    zero_deg_kernel<<<112, 256>>>(N);
    zero_stats_kernel<<<1, 128>>>();
    edge_kernel<<<(E * 4 + 255) / 256, 256>>>(             // launch #4 -> profiled
        (const float4*)node_feats, (const float4*)edge_feats, src, dst, E);

    int nblk = (N + 127) / 128;
    gemm1_kernel<<<nblk, 256, sm1>>>(node_feats, eps, W1, N);
    gemm2_kernel<<<nblk, 256, sm2>>>(W2, gamma1, beta1, out, N, invN);
    bn2_kernel<<<(N * 16 + 255) / 256, 256>>>(out, gamma2, beta2, N, invN);
}

// round 17
// speedup vs baseline: 1.0826x; 1.0826x over previous
#include <cuda_runtime.h>
#include <cuda_bf16.h>
#include <mma.h>
#include <cstdint>

using namespace nvcuda;

// ---------------- problem-size constants (dataset: N=100000, E=1600000, D=64) ----
#define MAXN 100000
#define DD   64
#define DD2  128

// ---------------- scratch (device-code-only references!) ---------------------------
__device__ float g_agg[(size_t)MAXN * DD];     // 25.6 MB  segment sums
__device__ float g_deg[MAXN];
__device__ float g_t1[(size_t)MAXN * DD2];     // 51.2 MB  pre-BN GEMM1 output (bias-free; BN shift-invariant)
__device__ float g_sum1[DD2], g_sumsq1[DD2];
__device__ float g_sum2[DD],  g_sumsq2[DD];

__device__ __forceinline__ uint32_t bfpack(float a, float b) {
    __nv_bfloat162 t = __floats2bfloat162_rn(a, b);
    return *reinterpret_cast<uint32_t*>(&t);
}

// ---------------- kernel 0: zero scratch (merged; edge is launch #2) ---------------
__global__ void zero_kernel(int n) {
    int stride = gridDim.x * blockDim.x;
    int i = blockIdx.x * blockDim.x + threadIdx.x;
    int total4 = n * 16;
    float4 z4 = make_float4(0.f, 0.f, 0.f, 0.f);
    for (int idx = i; idx < total4; idx += stride)
        reinterpret_cast<float4*>(g_agg)[idx] = z4;
    for (int idx = i; idx < n; idx += stride) g_deg[idx] = 0.0f;
    if (i < DD2) { g_sum1[i] = 0.0f; g_sumsq1[i] = 0.0f; }
    if (i < DD)  { g_sum2[i] = 0.0f; g_sumsq2[i] = 0.0f; }
}

// ---------------- kernel 1: edge gather + scatter (8 thr/edge, 2 float4 each) ------
// ROUND-15 VERSION (measured 103.9us): MLP=4 is the L1tex-queue sweet spot;
// MLP=8 regressed (L1 81%, issue 11%). indices leader-loaded + shfl broadcast.
__global__ void __launch_bounds__(256) edge_kernel(
    const float4* __restrict__ nf, const float4* __restrict__ ef,
    const int* __restrict__ src, const int* __restrict__ dst, int E)
{
    int t = blockIdx.x * blockDim.x + threadIdx.x;
    int lane = threadIdx.x & 31;
    int e = t >> 3;            // 8 threads per edge
    int q = t & 7;             // quarter index 0..7 (handles q and q+8)

    // leader lane of each 8-lane group loads indices; broadcast before any exit
    int sld = 0, dld = 0;
    if ((lane & 7) == 0 && e < E) { sld = __ldg(src + e); dld = __ldg(dst + e); }
    int s = __shfl_sync(0xffffffffu, sld, lane & ~7);
    int d = __shfl_sync(0xffffffffu, dld, lane & ~7);
    if (e >= E) return;

    size_t eb = (size_t)e * 16;
    size_t sb = (size_t)s * 16;
    // issue all 4 loads before any use (MLP=4)
    float4 b0 = __ldcs(ef + eb + q);
    float4 b1 = __ldcs(ef + eb + q + 8);
    float4 a0 = __ldg(nf + sb + q);
    float4 a1 = __ldg(nf + sb + q + 8);

    float4 v0 = make_float4(a0.x + b0.x, a0.y + b0.y, a0.z + b0.z, a0.w + b0.w);
    float4 v1 = make_float4(a1.x + b1.x, a1.y + b1.y, a1.z + b1.z, a1.w + b1.w);
    float4* aggp = reinterpret_cast<float4*>(g_agg) + (size_t)d * 16;
    atomicAdd(aggp + q, v0);
    atomicAdd(aggp + q + 8, v1);
    if (q == 0) atomicAdd(&g_deg[d], 1.0f);
}

// ---------------- kernel 2: combine + GEMM1 via WMMA bf16x3 + fused stats ----------
// A = h split hi/lo [128 rows][64 k] stride 72; B = W1 split [64 k][128 n] stride 136
#define AS1 72
#define BS1 136
__global__ void __launch_bounds__(256) gemm1_kernel(
    const float* __restrict__ nf, const float* __restrict__ eps,
    const float* __restrict__ W1, int N)
{
    extern __shared__ char smraw[];
    __nv_bfloat16* aHi = reinterpret_cast<__nv_bfloat16*>(smraw);
    __nv_bfloat16* aLo = aHi + 128 * AS1;
    __nv_bfloat16* bHi = aLo + 128 * AS1;
    __nv_bfloat16* bLo = bHi + 64 * BS1;
    float* stage = reinterpret_cast<float*>(smraw);   // reused after MMA
    __shared__ float s_sum[DD2], s_sumsq[DD2];

    int tid  = threadIdx.x;
    int w    = tid >> 5;
    int lane = tid & 31;
    int r0   = blockIdx.x * 128;
    float epsv = 1.0f + eps[0];
    if (tid < DD2) { s_sum[tid] = 0.f; s_sumsq[tid] = 0.f; }

    // build A: h = (1+eps)*nf + agg/max(deg,1), split hi/lo (coalesced)
    for (int c = tid; c < 128 * 16; c += 256) {
        int row = c >> 4;              // 0..127
        int kc  = (c & 15) << 2;       // 0,4,...,60
        int rg  = r0 + row;
        float4 v = make_float4(0.f, 0.f, 0.f, 0.f);
        if (rg < N) {
            float4 a = *reinterpret_cast<const float4*>(nf + (size_t)rg * DD + kc);
            float4 g = *reinterpret_cast<const float4*>(g_agg + (size_t)rg * DD + kc);
            float rd = 1.0f / fmaxf(g_deg[rg], 1.0f);
            v.x = epsv * a.x + g.x * rd;
            v.y = epsv * a.y + g.y * rd;
            v.z = epsv * a.z + g.z * rd;
            v.w = epsv * a.w + g.w * rd;
        }
        float hx = __bfloat162float(__float2bfloat16_rn(v.x));
        float hy = __bfloat162float(__float2bfloat16_rn(v.y));
        float hz = __bfloat162float(__float2bfloat16_rn(v.z));
        float hw = __bfloat162float(__float2bfloat16_rn(v.w));
        *reinterpret_cast<uint32_t*>(aHi + row * AS1 + kc)     = bfpack(hx, hy);
        *reinterpret_cast<uint32_t*>(aHi + row * AS1 + kc + 2) = bfpack(hz, hw);
        *reinterpret_cast<uint32_t*>(aLo + row * AS1 + kc)     = bfpack(v.x - hx, v.y - hy);
        *reinterpret_cast<uint32_t*>(aLo + row * AS1 + kc + 2) = bfpack(v.z - hz, v.w - hw);
    }

    // build B[k][n] = W1 (row-major [64][128] already k-major) — coalesced
    for (int c = tid; c < 64 * 64; c += 256) {
        int k  = c >> 6;
        int n2 = (c & 63) << 1;
        float w0 = __ldg(W1 + k * 128 + n2);
        float w1 = __ldg(W1 + k * 128 + n2 + 1);
        float h0 = __bfloat162float(__float2bfloat16_rn(w0));
        float h1 = __bfloat162float(__float2bfloat16_rn(w1));
        *reinterpret_cast<uint32_t*>(bHi + k * BS1 + n2) = bfpack(h0, h1);
        *reinterpret_cast<uint32_t*>(bLo + k * BS1 + n2) = bfpack(w0 - h0, w1 - h1);
    }
    __syncthreads();

    // MMA: warp w owns rows [w*16, w*16+16)
    int rbase = w * 16;
    wmma::fragment<wmma::accumulator, 16, 16, 16, float> acc[8];
#pragma unroll
    for (int j = 0; j < 8; j++) wmma::fill_fragment(acc[j], 0.0f);

#pragma unroll
    for (int k0 = 0; k0 < 64; k0 += 16) {
        wmma::fragment<wmma::matrix_a, 16, 16, 16, __nv_bfloat16, wmma::row_major> fah, fal;
        wmma::load_matrix_sync(fah, aHi + rbase * AS1 + k0, AS1);
        wmma::load_matrix_sync(fal, aLo + rbase * AS1 + k0, AS1);
#pragma unroll
        for (int j = 0; j < 8; j++) {
            wmma::fragment<wmma::matrix_b, 16, 16, 16, __nv_bfloat16, wmma::row_major> fbh, fbl;
            wmma::load_matrix_sync(fbh, bHi + k0 * BS1 + j * 16, BS1);
            wmma::load_matrix_sync(fbl, bLo + k0 * BS1 + j * 16, BS1);
            wmma::mma_sync(acc[j], fah, fbh, acc[j]);
            wmma::mma_sync(acc[j], fah, fbl, acc[j]);
            wmma::mma_sync(acc[j], fal, fbh, acc[j]);
        }
    }
    __syncthreads();   // done reading A/B; reuse smem as f32 staging

    float* st = stage + w * (16 * BS1);
#pragma unroll
    for (int j = 0; j < 8; j++)
        wmma::store_matrix_sync(st + j * 16, acc[j], BS1, wmma::mem_row_major);
    __syncwarp();

    // guarded copy to g_t1 + fused column stats (lane owns cols [lane*4, +4))
    {
        int col = lane << 2;
        float4 cs = make_float4(0.f, 0.f, 0.f, 0.f);
        float4 cq = make_float4(0.f, 0.f, 0.f, 0.f);
#pragma unroll
        for (int rr = 0; rr < 16; rr++) {
            int rg = r0 + rbase + rr;
            if (rg < N) {
                float4 v = *reinterpret_cast<float4*>(st + rr * BS1 + col);
                *reinterpret_cast<float4*>(g_t1 + (size_t)rg * DD2 + col) = v;
                cs.x += v.x; cs.y += v.y; cs.z += v.z; cs.w += v.w;
                cq.x += v.x * v.x; cq.y += v.y * v.y;
                cq.z += v.z * v.z; cq.w += v.w * v.w;
            }
        }
        atomicAdd(&s_sum[col + 0], cs.x); atomicAdd(&s_sum[col + 1], cs.y);
        atomicAdd(&s_sum[col + 2], cs.z); atomicAdd(&s_sum[col + 3], cs.w);
        atomicAdd(&s_sumsq[col + 0], cq.x); atomicAdd(&s_sumsq[col + 1], cq.y);
        atomicAdd(&s_sumsq[col + 2], cq.z); atomicAdd(&s_sumsq[col + 3], cq.w);
    }
    __syncthreads();
    if (tid < DD2) {
        atomicAdd(&g_sum1[tid], s_sum[tid]);
        atomicAdd(&g_sumsq1[tid], s_sumsq[tid]);
    }
}

// ---------------- kernel 3: BN1+ReLU + GEMM2, K=128 in TWO 64-halves ---------------
// smem per half: A 2x128x72 bf16 + B 2x64x72 bf16 = 55.3KB -> 4 blocks/SM.
// Launch #4 -> gets profiled this round.
#define AS2 72
#define BS2 72
__global__ void __launch_bounds__(256) gemm2_kernel(
    const float* __restrict__ W2,
    const float* __restrict__ gamma1, const float* __restrict__ beta1,
    float* __restrict__ out, int N, float invN)
{
    extern __shared__ char smraw[];
    __nv_bfloat16* aHi = reinterpret_cast<__nv_bfloat16*>(smraw);
    __nv_bfloat16* aLo = aHi + 128 * AS2;
    __nv_bfloat16* bHi = aLo + 128 * AS2;
    __nv_bfloat16* bLo = bHi + 64 * BS2;
    float* stage = reinterpret_cast<float*>(smraw);   // aliases A region
    __shared__ float s_scale[DD2], s_shift[DD2];
    __shared__ float s_sum[DD], s_sumsq[DD];

    int tid  = threadIdx.x;
    int w    = tid >> 5;
    int lane = tid & 31;
    int r0   = blockIdx.x * 128;

    if (tid < DD) { s_sum[tid] = 0.f; s_sumsq[tid] = 0.f; }
    if (tid < DD2) {
        float m = g_sum1[tid] * invN;
        float v = fmaxf(g_sumsq1[tid] * invN - m * m, 0.0f);
        float sc = __ldg(gamma1 + tid) * rsqrtf(v + 1e-5f);
        s_scale[tid] = sc;
        s_shift[tid] = __ldg(beta1 + tid) - m * sc;
    }

    int rbase = w * 16;
    wmma::fragment<wmma::accumulator, 16, 16, 16, float> acc[4];
#pragma unroll
    for (int j = 0; j < 4; j++) wmma::fill_fragment(acc[j], 0.0f);

#pragma unroll
    for (int kh = 0; kh < 2; kh++) {
        __syncthreads();   // covers s_scale on first pass, tile reuse after

        // build A half = relu(BN1(t1[:, kh*64 : +64])) split hi/lo (coalesced)
        for (int c = tid; c < 128 * 16; c += 256) {
            int row = c >> 4;              // 0..127
            int kl  = (c & 15) << 2;       // local k 0..60
            int kg  = kh * 64 + kl;
            int rg  = r0 + row;
            float4 v = make_float4(0.f, 0.f, 0.f, 0.f);
            if (rg < N) {
                float4 z = *reinterpret_cast<const float4*>(g_t1 + (size_t)rg * DD2 + kg);
                v.x = fmaxf(fmaf(z.x, s_scale[kg + 0], s_shift[kg + 0]), 0.f);
                v.y = fmaxf(fmaf(z.y, s_scale[kg + 1], s_shift[kg + 1]), 0.f);
                v.z = fmaxf(fmaf(z.z, s_scale[kg + 2], s_shift[kg + 2]), 0.f);
                v.w = fmaxf(fmaf(z.w, s_scale[kg + 3], s_shift[kg + 3]), 0.f);
            }
            float hx = __bfloat162float(__float2bfloat16_rn(v.x));
            float hy = __bfloat162float(__float2bfloat16_rn(v.y));
            float hz = __bfloat162float(__float2bfloat16_rn(v.z));
            float hw = __bfloat162float(__float2bfloat16_rn(v.w));
            *reinterpret_cast<uint32_t*>(aHi + row * AS2 + kl)     = bfpack(hx, hy);
            *reinterpret_cast<uint32_t*>(aHi + row * AS2 + kl + 2) = bfpack(hz, hw);
            *reinterpret_cast<uint32_t*>(aLo + row * AS2 + kl)     = bfpack(v.x - hx, v.y - hy);
            *reinterpret_cast<uint32_t*>(aLo + row * AS2 + kl + 2) = bfpack(v.z - hz, v.w - hw);
        }

        // build B half: k in [kh*64, +64) rows of W2[128][64], stride 72 (coalesced)
        for (int c = tid; c < 64 * 32; c += 256) {
            int k  = c >> 5;               // local k 0..63
            int n2 = (c & 31) << 1;
            int kg = kh * 64 + k;
            float w0 = __ldg(W2 + kg * 64 + n2);
            float w1 = __ldg(W2 + kg * 64 + n2 + 1);
            float h0 = __bfloat162float(__float2bfloat16_rn(w0));
            float h1 = __bfloat162float(__float2bfloat16_rn(w1));
            *reinterpret_cast<uint32_t*>(bHi + k * BS2 + n2) = bfpack(h0, h1);
            *reinterpret_cast<uint32_t*>(bLo + k * BS2 + n2) = bfpack(w0 - h0, w1 - h1);
        }
        __syncthreads();

#pragma unroll
        for (int k0 = 0; k0 < 64; k0 += 16) {
            wmma::fragment<wmma::matrix_a, 16, 16, 16, __nv_bfloat16, wmma::row_major> fah, fal;
            wmma::load_matrix_sync(fah, aHi + rbase * AS2 + k0, AS2);
            wmma::load_matrix_sync(fal, aLo + rbase * AS2 + k0, AS2);
#pragma unroll
            for (int j = 0; j < 4; j++) {
                wmma::fragment<wmma::matrix_b, 16, 16, 16, __nv_bfloat16, wmma::row_major> fbh, fbl;
                wmma::load_matrix_sync(fbh, bHi + k0 * BS2 + j * 16, BS2);
                wmma::load_matrix_sync(fbl, bLo + k0 * BS2 + j * 16, BS2);
                wmma::mma_sync(acc[j], fah, fbh, acc[j]);
                wmma::mma_sync(acc[j], fah, fbl, acc[j]);
                wmma::mma_sync(acc[j], fal, fbh, acc[j]);
            }
        }
    }
    __syncthreads();   // done with A/B; reuse smem as f32 staging

    float* st = stage + w * (16 * BS2);
#pragma unroll
    for (int j = 0; j < 4; j++)
        wmma::store_matrix_sync(st + j * 16, acc[j], BS2, wmma::mem_row_major);
    __syncwarp();

    // guarded copy to out + fused column stats (col = (lane&15)*4, row halves)
    {
        int col = (lane & 15) << 2;
        int rhalf = (lane >> 4) * 8;
        float4 cs = make_float4(0.f, 0.f, 0.f, 0.f);
        float4 cq = make_float4(0.f, 0.f, 0.f, 0.f);
#pragma unroll
        for (int rr = 0; rr < 8; rr++) {
            int r = rhalf + rr;
            int rg = r0 + rbase + r;
            if (rg < N) {
                float4 v = *reinterpret_cast<float4*>(st + r * BS2 + col);
                *reinterpret_cast<float4*>(out + (size_t)rg * DD + col) = v;
                cs.x += v.x; cs.y += v.y; cs.z += v.z; cs.w += v.w;
                cq.x += v.x * v.x; cq.y += v.y * v.y;
                cq.z += v.z * v.z; cq.w += v.w * v.w;
            }
        }
        atomicAdd(&s_sum[col + 0], cs.x); atomicAdd(&s_sum[col + 1], cs.y);
        atomicAdd(&s_sum[col + 2], cs.z); atomicAdd(&s_sum[col + 3], cs.w);
        atomicAdd(&s_sumsq[col + 0], cq.x); atomicAdd(&s_sumsq[col + 1], cq.y);
        atomicAdd(&s_sumsq[col + 2], cq.z); atomicAdd(&s_sumsq[col + 3], cq.w);
    }
    __syncthreads();
    if (tid < DD) {
        atomicAdd(&g_sum2[tid], s_sum[tid]);
        atomicAdd(&g_sumsq2[tid], s_sumsq[tid]);
    }
}

// ---------------- kernel 4: BN2 finalize (folded) + BN2 + ReLU in place ------------
__global__ void __launch_bounds__(256) bn2_kernel(
    float* __restrict__ out, const float* __restrict__ gamma2,
    const float* __restrict__ beta2, int N, float invN)
{
    __shared__ float s_scale2[DD], s_shift2[DD];
    int tid = threadIdx.x;
    if (tid < DD) {
        float m = g_sum2[tid] * invN;
        float v = fmaxf(g_sumsq2[tid] * invN - m * m, 0.0f);
        float sc = __ldg(gamma2 + tid) * rsqrtf(v + 1e-5f);
        s_scale2[tid] = sc;
        s_shift2[tid] = __ldg(beta2 + tid) - m * sc;
    }
    __syncthreads();

    int idx = blockIdx.x * blockDim.x + tid;
    int total = N * 16;
    if (idx >= total) return;
    int c = (idx & 15) << 2;
    float4 z = reinterpret_cast<float4*>(out)[idx];
    z.x = fmaxf(fmaf(z.x, s_scale2[c + 0], s_shift2[c + 0]), 0.f);
    z.y = fmaxf(fmaf(z.y, s_scale2[c + 1], s_shift2[c + 1]), 0.f);
    z.z = fmaxf(fmaf(z.z, s_scale2[c + 2], s_shift2[c + 2]), 0.f);
    z.w = fmaxf(fmaf(z.w, s_scale2[c + 3], s_shift2[c + 3]), 0.f);
    reinterpret_cast<float4*>(out)[idx] = z;
}

// ---------------- launch ------------------------------------------------------------
extern "C" void kernel_launch(void* const* d_in, const int* in_sizes, int n_in,
                              void* d_out, int out_size) {
    const float* node_feats = (const float*)d_in[0];
    const float* edge_feats = (const float*)d_in[1];
    const int*   src        = (const int*)d_in[2];
    const int*   dst        = (const int*)d_in[3];
    const float* eps        = (const float*)d_in[4];
    const float* W1         = (const float*)d_in[5];
    const float* gamma1     = (const float*)d_in[7];
    const float* beta1      = (const float*)d_in[8];
    const float* W2         = (const float*)d_in[9];
    const float* gamma2     = (const float*)d_in[11];
    const float* beta2      = (const float*)d_in[12];
    float* out = (float*)d_out;

    int N = in_sizes[0] / DD;
    int E = in_sizes[1] / DD;
    float invN = 1.0f / (float)N;

    size_t sm1 = (size_t)(2 * 128 * AS1 + 2 * 64 * BS1) * 2;    // 71680 B
    size_t sm2 = (size_t)(2 * 128 * AS2 + 2 * 64 * BS2) * 2;    // 55296 B
    cudaFuncSetAttribute(gemm1_kernel, cudaFuncAttributeMaxDynamicSharedMemorySize, (int)sm1);
    cudaFuncSetAttribute(gemm2_kernel, cudaFuncAttributeMaxDynamicSharedMemorySize, (int)sm2);

    zero_kernel<<<4096, 256>>>(N);
    edge_kernel<<<(E * 8 + 255) / 256, 256>>>(
        (const float4*)node_feats, (const float4*)edge_feats, src, dst, E);

    int nblk = (N + 127) / 128;
    gemm1_kernel<<<nblk, 256, sm1>>>(node_feats, eps, W1, N);
    gemm2_kernel<<<nblk, 256, sm2>>>(W2, gamma1, beta1, out, N, invN);   // launch #4
    bn2_kernel<<<(N * 16 + 255) / 256, 256>>>(out, gamma2, beta2, N, invN);
}